// round 10
// baseline (speedup 1.0000x reference)
#include <cuda_runtime.h>
#include <cuda_fp16.h>
#include <math.h>

#define D 128
#define MAX_N_STU 100000
#define MAX_N_ITEM 20000
#define MAX_E_R 500000
#define MAX_E_P 300000
#define SAH 136    // half stride: 272B rows -> conflict-free ldmatrix row fetch
#define TILE_M 64  // A-tile rows per block

// ---------------- scratch ------------------------------------------------------
__device__ __half g_hx_stu[(size_t)MAX_N_STU * D];
__device__ __half g_hx_item[(size_t)MAX_N_ITEM * D];
__device__ __half g_Yh[(size_t)MAX_N_ITEM * D];
__device__ __half g_meanI_h[(size_t)MAX_N_ITEM * D];
__device__ __half g_meanY_h[(size_t)MAX_N_STU * D];
__device__ __half g_Hmean_h[(size_t)MAX_N_STU * D];
__device__ float g_R[(size_t)MAX_N_STU * D];
__device__ float g_Q[(size_t)MAX_N_STU * D];
__device__ float g_stats[4 * D];

// CSR scratch
__device__ int g_deg_item[MAX_N_ITEM];
__device__ int g_rp_item[MAX_N_ITEM + 1];
__device__ int g_cur_item[MAX_N_ITEM];
__device__ int g_adj_item[MAX_E_R];
__device__ int g_deg_rs[MAX_N_STU];
__device__ int g_rp_rs[MAX_N_STU + 1];
__device__ int g_cur_rs[MAX_N_STU];
__device__ int g_adj_rs[MAX_E_R];
__device__ int g_deg_p[MAX_N_STU];
__device__ int g_rp_p[MAX_N_STU + 1];
__device__ int g_cur_p[MAX_N_STU];
__device__ int g_adj_p[MAX_E_P];

// ---------------- fp32 -> fp16 convert ----------------------------------------
__global__ void f2h_kernel(const float* __restrict__ X, __half* __restrict__ H,
                           size_t n4) {
    size_t i = blockIdx.x * (size_t)blockDim.x + threadIdx.x;
    size_t stride = (size_t)gridDim.x * blockDim.x;
    for (; i < n4; i += stride) {
        float4 v = ((const float4*)X)[i];
        __half2* p = (__half2*)H + 2 * i;
        p[0] = __floats2half2_rn(v.x, v.y);
        p[1] = __floats2half2_rn(v.z, v.w);
    }
}

// ---------------- small zero ---------------------------------------------------
__global__ void zero_small_kernel() {
    int i = blockIdx.x * blockDim.x + threadIdx.x;
    int stride = gridDim.x * blockDim.x;
    for (int x = i; x < MAX_N_STU; x += stride) {
        g_deg_rs[x] = 0;
        g_deg_p[x] = 0;
        if (x < MAX_N_ITEM) g_deg_item[x] = 0;
        if (x < 4 * D) g_stats[x] = 0.f;
    }
}

// ---------------- CSR build ----------------------------------------------------
__global__ void hist_kernel(const int* __restrict__ rsrc, const int* __restrict__ rdst,
                            int eR, const int* __restrict__ pdst, int eP) {
    int i = blockIdx.x * blockDim.x + threadIdx.x;
    if (i < eR) {
        atomicAdd(&g_deg_item[rdst[i]], 1);
        atomicAdd(&g_deg_rs[rsrc[i]], 1);
    }
    if (i < eP) atomicAdd(&g_deg_p[pdst[i]], 1);
}

__global__ __launch_bounds__(1024) void scan3_kernel(int n_item, int n_stu) {
    int n;
    int *deg, *rp, *cur;
    if (blockIdx.x == 0) { n = n_item; deg = g_deg_item; rp = g_rp_item; cur = g_cur_item; }
    else if (blockIdx.x == 1) { n = n_stu; deg = g_deg_rs; rp = g_rp_rs; cur = g_cur_rs; }
    else { n = n_stu; deg = g_deg_p; rp = g_rp_p; cur = g_cur_p; }

    __shared__ int warpSums[32];
    int chunk = (n + 1023) >> 10;
    int begin = min((int)threadIdx.x * chunk, n);
    int end = min(begin + chunk, n);
    int s = 0;
    for (int i = begin; i < end; i++) s += deg[i];
    int lane = threadIdx.x & 31, w = threadIdx.x >> 5;
    int v = s;
#pragma unroll
    for (int o = 1; o < 32; o <<= 1) {
        int t = __shfl_up_sync(0xffffffffu, v, o);
        if (lane >= o) v += t;
    }
    if (lane == 31) warpSums[w] = v;
    __syncthreads();
    if (w == 0) {
        int t = warpSums[lane];
#pragma unroll
        for (int o = 1; o < 32; o <<= 1) {
            int u = __shfl_up_sync(0xffffffffu, t, o);
            if (lane >= o) t += u;
        }
        warpSums[lane] = t;
    }
    __syncthreads();
    int excl = v - s + (w > 0 ? warpSums[w - 1] : 0);
    int run = excl;
    for (int i = begin; i < end; i++) {
        rp[i] = run;
        cur[i] = run;
        run += deg[i];
    }
    if (begin < n && end == n) rp[n] = run;
}

__global__ void fill_kernel(const int* __restrict__ rsrc, const int* __restrict__ rdst,
                            int eR, const int* __restrict__ psrc,
                            const int* __restrict__ pdst, int eP) {
    int i = blockIdx.x * blockDim.x + threadIdx.x;
    if (i < eR) {
        int s = rsrc[i], d = rdst[i];
        g_adj_item[atomicAdd(&g_cur_item[d], 1)] = s;
        g_adj_rs[atomicAdd(&g_cur_rs[s], 1)] = d;
    }
    if (i < eP) {
        g_adj_p[atomicAdd(&g_cur_p[pdst[i]], 1)] = psrc[i];
    }
}

// ---------------- CSR gather (half features, warp/node, 8-way MLP) -------------
__device__ __forceinline__ float2 u2f2(unsigned u) {
    return __half22float2(*(__half2*)&u);
}

__global__ void agg_gather_h(const __half* __restrict__ X,
                             const int* __restrict__ rp,
                             const int* __restrict__ adj,
                             __half* __restrict__ out, int N) {
    int node = (blockIdx.x * blockDim.x + threadIdx.x) >> 5;
    if (node >= N) return;
    int lane = threadIdx.x & 31;
    int b = rp[node], e = rp[node + 1];
    float a0 = 0.f, a1 = 0.f, a2 = 0.f, a3 = 0.f;
    int i = b;
    for (; i + 8 <= e; i += 8) {
        uint2 v[8];
#pragma unroll
        for (int j = 0; j < 8; j++) {
            int n = __ldg(adj + i + j);
            v[j] = ((const uint2*)(X + (size_t)n * D))[lane];
        }
#pragma unroll
        for (int j = 0; j < 8; j++) {
            float2 p = u2f2(v[j].x), q = u2f2(v[j].y);
            a0 += p.x; a1 += p.y; a2 += q.x; a3 += q.y;
        }
    }
    for (; i < e; i++) {
        int n = __ldg(adj + i);
        uint2 v = ((const uint2*)(X + (size_t)n * D))[lane];
        float2 p = u2f2(v.x), q = u2f2(v.y);
        a0 += p.x; a1 += p.y; a2 += q.x; a3 += q.y;
    }
    float inv = 1.f / (float)max(e - b, 1);
    __half2* o = (__half2*)(out + (size_t)node * D) + 2 * lane;
    o[0] = __floats2half2_rn(a0 * inv, a1 * inv);
    o[1] = __floats2half2_rn(a2 * inv, a3 * inv);
}

__device__ __forceinline__ float elu1(float x) {
    return x > 0.f ? x : expm1f(x);
}

// Hmean[d] = mean_s elu(R[s] + Q[d] + b1)   (fp32 R/Q in, half out)
__global__ void simple_gather_kernel(const float* __restrict__ R,
                                     const float* __restrict__ Q,
                                     const float* __restrict__ b1,
                                     const int* __restrict__ rp,
                                     const int* __restrict__ adj,
                                     __half* __restrict__ Hmean, int N) {
    int node = (blockIdx.x * blockDim.x + threadIdx.x) >> 5;
    if (node >= N) return;
    int lane = threadIdx.x & 31;
    int b = rp[node], e = rp[node + 1];
    float4 qd = ((const float4*)(Q + (size_t)node * D))[lane];
    float4 bb = ((const float4*)b1)[lane];
    qd.x += bb.x; qd.y += bb.y; qd.z += bb.z; qd.w += bb.w;
    float4 acc = make_float4(0.f, 0.f, 0.f, 0.f);
    int i = b;
    for (; i + 4 <= e; i += 4) {
        int n0 = __ldg(adj + i), n1 = __ldg(adj + i + 1);
        int n2 = __ldg(adj + i + 2), n3 = __ldg(adj + i + 3);
        float4 v0 = ((const float4*)(R + (size_t)n0 * D))[lane];
        float4 v1 = ((const float4*)(R + (size_t)n1 * D))[lane];
        float4 v2 = ((const float4*)(R + (size_t)n2 * D))[lane];
        float4 v3 = ((const float4*)(R + (size_t)n3 * D))[lane];
        acc.x += elu1(v0.x + qd.x) + elu1(v1.x + qd.x) + elu1(v2.x + qd.x) + elu1(v3.x + qd.x);
        acc.y += elu1(v0.y + qd.y) + elu1(v1.y + qd.y) + elu1(v2.y + qd.y) + elu1(v3.y + qd.y);
        acc.z += elu1(v0.z + qd.z) + elu1(v1.z + qd.z) + elu1(v2.z + qd.z) + elu1(v3.z + qd.z);
        acc.w += elu1(v0.w + qd.w) + elu1(v1.w + qd.w) + elu1(v2.w + qd.w) + elu1(v3.w + qd.w);
    }
    for (; i < e; i++) {
        int n = __ldg(adj + i);
        float4 v = ((const float4*)(R + (size_t)n * D))[lane];
        acc.x += elu1(v.x + qd.x);
        acc.y += elu1(v.y + qd.y);
        acc.z += elu1(v.z + qd.z);
        acc.w += elu1(v.w + qd.w);
    }
    float inv = 1.f / (float)max(e - b, 1);
    __half2* o = (__half2*)(Hmean + (size_t)node * D) + 2 * lane;
    o[0] = __floats2half2_rn(acc.x * inv, acc.y * inv);
    o[1] = __floats2half2_rn(acc.z * inv, acc.w * inv);
}

// ---------------- fp16 tensor-core GEMM pieces ---------------------------------
__device__ __forceinline__ void stage_A_hh(const __half* __restrict__ A, int M,
                                           int rowBase, __half* sA) {
    for (int i = threadIdx.x; i < TILE_M * 32; i += 256) {
        int r = i >> 5, c = i & 31;
        int gr = rowBase + r;
        uint2 v = make_uint2(0u, 0u);
        if (gr < M) v = ((const uint2*)(A + (size_t)gr * D))[c];
        *(uint2*)(sA + r * SAH + c * 4) = v;
    }
}

__device__ __forceinline__ void stage_Wt_h(const float* __restrict__ W,
                                           const float* __restrict__ Wb,
                                           __half* sWt) {
    for (int i = threadIdx.x; i < 128 * 32; i += 256) {
        int k = i & 127, n4 = i >> 7;
        float4 v = ((const float4*)(W + (size_t)k * D))[n4];
        if (Wb) {
            float4 b = ((const float4*)(Wb + (size_t)k * D))[n4];
            v.x -= b.x; v.y -= b.y; v.z -= b.z; v.w -= b.w;
        }
        sWt[(n4 * 4 + 0) * SAH + k] = __float2half_rn(v.x);
        sWt[(n4 * 4 + 1) * SAH + k] = __float2half_rn(v.y);
        sWt[(n4 * 4 + 2) * SAH + k] = __float2half_rn(v.z);
        sWt[(n4 * 4 + 3) * SAH + k] = __float2half_rn(v.w);
    }
}

#define LDSM_X4(r0, r1, r2, r3, addr) \
    asm volatile("ldmatrix.sync.aligned.m8n8.x4.shared.b16 {%0,%1,%2,%3}, [%4];" \
                 : "=r"(r0), "=r"(r1), "=r"(r2), "=r"(r3) : "r"(addr))

// m32n32 warp tile via mma.m16n8k16 f16->f32, ldmatrix fragment loads.
__device__ __forceinline__ void mm_h32(const __half* sA, const __half* sWt,
                                       float acc[2][4][4]) {
    int lane = threadIdx.x & 31, w = threadIdx.x >> 5;
    int rg = w >> 2, cg = w & 3;
    // A: lanes 0-15 -> rows (l&15) at k0; lanes 16-31 -> same rows at k0+8.
    unsigned aBase[2];
#pragma unroll
    for (int mi = 0; mi < 2; mi++)
        aBase[mi] = (unsigned)__cvta_generic_to_shared(
            sA + (rg * 32 + mi * 16 + (lane & 15)) * SAH + ((lane >> 4) << 3));
    // B: x4 covers j-pair (2jp, 2jp+1): lanes0-7 j=2jp k0, 8-15 j=2jp k0+8,
    //    16-23 j=2jp+1 k0, 24-31 j=2jp+1 k0+8.
    unsigned bBase[2];
    int bj = (lane >> 4);
    int bk = ((lane >> 3) & 1) << 3;
#pragma unroll
    for (int jp = 0; jp < 2; jp++)
        bBase[jp] = (unsigned)__cvta_generic_to_shared(
            sWt + (cg * 32 + (2 * jp + bj) * 8 + (lane & 7)) * SAH + bk);
#pragma unroll
    for (int k0 = 0; k0 < 128; k0 += 16) {
        unsigned a[2][4], b[2][4];
#pragma unroll
        for (int mi = 0; mi < 2; mi++)
            LDSM_X4(a[mi][0], a[mi][1], a[mi][2], a[mi][3], aBase[mi] + 2 * k0);
#pragma unroll
        for (int jp = 0; jp < 2; jp++)
            LDSM_X4(b[jp][0], b[jp][1], b[jp][2], b[jp][3], bBase[jp] + 2 * k0);
#pragma unroll
        for (int jp = 0; jp < 2; jp++) {
#pragma unroll
            for (int sub = 0; sub < 2; sub++) {
                int j = 2 * jp + sub;
                unsigned b0 = b[jp][2 * sub], b1 = b[jp][2 * sub + 1];
#pragma unroll
                for (int mi = 0; mi < 2; mi++) {
                    asm volatile(
                        "mma.sync.aligned.m16n8k16.row.col.f32.f16.f16.f32 "
                        "{%0,%1,%2,%3},{%4,%5,%6,%7},{%8,%9},{%0,%1,%2,%3};"
                        : "+f"(acc[mi][j][0]), "+f"(acc[mi][j][1]),
                          "+f"(acc[mi][j][2]), "+f"(acc[mi][j][3])
                        : "r"(a[mi][0]), "r"(a[mi][1]), "r"(a[mi][2]), "r"(a[mi][3]),
                          "r"(b0), "r"(b1));
                }
            }
        }
    }
}

__device__ __forceinline__ void store_tile_f(float* __restrict__ C, int M, int rowBase,
                                             float acc[2][4][4]) {
    int lane = threadIdx.x & 31, w = threadIdx.x >> 5;
    int g = lane >> 2, t = lane & 3;
    int rg = w >> 2, cg = w & 3;
#pragma unroll
    for (int mi = 0; mi < 2; mi++) {
        int rA = rowBase + rg * 32 + mi * 16 + g, rB = rA + 8;
#pragma unroll
        for (int j = 0; j < 4; j++) {
            int c = cg * 32 + j * 8 + 2 * t;
            if (rA < M) *(float2*)(C + (size_t)rA * D + c) = make_float2(acc[mi][j][0], acc[mi][j][1]);
            if (rB < M) *(float2*)(C + (size_t)rB * D + c) = make_float2(acc[mi][j][2], acc[mi][j][3]);
        }
    }
}

__device__ __forceinline__ void store_tile_h(__half* __restrict__ C, int M, int rowBase,
                                             float acc[2][4][4]) {
    int lane = threadIdx.x & 31, w = threadIdx.x >> 5;
    int g = lane >> 2, t = lane & 3;
    int rg = w >> 2, cg = w & 3;
#pragma unroll
    for (int mi = 0; mi < 2; mi++) {
        int rA = rowBase + rg * 32 + mi * 16 + g, rB = rA + 8;
#pragma unroll
        for (int j = 0; j < 4; j++) {
            int c = cg * 32 + j * 8 + 2 * t;
            if (rA < M) *(__half2*)(C + (size_t)rA * D + c) = __floats2half2_rn(acc[mi][j][0], acc[mi][j][1]);
            if (rB < M) *(__half2*)(C + (size_t)rB * D + c) = __floats2half2_rn(acc[mi][j][2], acc[mi][j][3]);
        }
    }
}

// Yh = hx_item @ W  (half in, half out)
__global__ __launch_bounds__(256, 3) void gemm_one_hh(const __half* __restrict__ A,
                                                      const float* __restrict__ W,
                                                      __half* __restrict__ C, int M) {
    extern __shared__ __half smem_h[];
    __half* sA = smem_h;
    __half* sW = smem_h + TILE_M * SAH;
    int rowBase = blockIdx.x * TILE_M;
    float acc[2][4][4] = {};
    stage_A_hh(A, M, rowBase, sA);
    stage_Wt_h(W, nullptr, sW);
    __syncthreads();
    mm_h32(sA, sW, acc);
    store_tile_h(C, M, rowBase, acc);
}

// R = x@(W1top - W1bot), Q = x@W1bot (half A in, fp32 out); shares A tile.
__global__ __launch_bounds__(256, 3) void gemm_rq_h(const __half* __restrict__ x,
                                                    const float* __restrict__ W1,
                                                    float* __restrict__ Rm,
                                                    float* __restrict__ Qm, int M) {
    extern __shared__ __half smem_h[];
    __half* sA = smem_h;
    __half* sW = smem_h + TILE_M * SAH;
    int rowBase = blockIdx.x * TILE_M;

    stage_A_hh(x, M, rowBase, sA);
    stage_Wt_h(W1 + 128 * D, nullptr, sW);
    __syncthreads();
    {
        float acc[2][4][4] = {};
        mm_h32(sA, sW, acc);
        store_tile_f(Qm, M, rowBase, acc);
    }
    __syncthreads();
    stage_Wt_h(W1, W1 + 128 * D, sW);
    __syncthreads();
    {
        float acc[2][4][4] = {};
        mm_h32(sA, sW, acc);
        store_tile_f(Rm, M, rowBase, acc);
    }
}

// smem + global reduction of per-column sums.
__device__ __forceinline__ void stats_reduce(float* sred, const float lsum[8],
                                             const float lss[8], int cg, int t,
                                             float* __restrict__ statSum,
                                             float* __restrict__ statSS) {
    __syncthreads();
    sred[threadIdx.x] = 0.f;
    __syncthreads();
#pragma unroll
    for (int j = 0; j < 4; j++) {
        int c = cg * 32 + j * 8 + 2 * t;
        atomicAdd(&sred[c], lsum[2 * j]);
        atomicAdd(&sred[c + 1], lsum[2 * j + 1]);
        atomicAdd(&sred[128 + c], lss[2 * j]);
        atomicAdd(&sred[128 + c + 1], lss[2 * j + 1]);
    }
    __syncthreads();
    if (threadIdx.x < 128) {
        atomicAdd(statSum + threadIdx.x, sred[threadIdx.x]);
        atomicAdd(statSS + threadIdx.x, sred[128 + threadIdx.x]);
    }
}

// item pre-BN = elu( meanI@Wl + x_item@Wr + b ) -> out fp32, + BN stats
__global__ __launch_bounds__(256, 3) void out_item_h(
    const __half* __restrict__ meanI, const __half* __restrict__ x_item,
    const float* __restrict__ Wl, const float* __restrict__ Wr,
    const float* __restrict__ b, float* __restrict__ out,
    float* __restrict__ stats, int M) {
    extern __shared__ __half smem_h[];
    __half* sA = smem_h;
    __half* sW = smem_h + TILE_M * SAH;
    int rowBase = blockIdx.x * TILE_M;
    float acc[2][4][4] = {};

    stage_A_hh(meanI, M, rowBase, sA);
    stage_Wt_h(Wl, nullptr, sW);
    __syncthreads();
    mm_h32(sA, sW, acc);
    __syncthreads();
    stage_A_hh(x_item, M, rowBase, sA);
    stage_Wt_h(Wr, nullptr, sW);
    __syncthreads();
    mm_h32(sA, sW, acc);

    int lane = threadIdx.x & 31, w = threadIdx.x >> 5;
    int g = lane >> 2, t = lane & 3;
    int rg = w >> 2, cg = w & 3;
    float lsum[8] = {}, lss[8] = {};
#pragma unroll
    for (int mi = 0; mi < 2; mi++) {
        int rA = rowBase + rg * 32 + mi * 16 + g, rB = rA + 8;
#pragma unroll
        for (int j = 0; j < 4; j++) {
            int c = cg * 32 + j * 8 + 2 * t;
            float b0v = b[c], b1v = b[c + 1];
            if (rA < M) {
                float e0 = elu1(acc[mi][j][0] + b0v);
                float e1 = elu1(acc[mi][j][1] + b1v);
                *(float2*)(out + (size_t)rA * D + c) = make_float2(e0, e1);
                lsum[2 * j] += e0; lss[2 * j] += e0 * e0;
                lsum[2 * j + 1] += e1; lss[2 * j + 1] += e1 * e1;
            }
            if (rB < M) {
                float e2 = elu1(acc[mi][j][2] + b0v);
                float e3 = elu1(acc[mi][j][3] + b1v);
                *(float2*)(out + (size_t)rB * D + c) = make_float2(e2, e3);
                lsum[2 * j] += e2; lss[2 * j] += e2 * e2;
                lsum[2 * j + 1] += e3; lss[2 * j + 1] += e3 * e3;
            }
        }
    }
    stats_reduce((float*)sA, lsum, lss, cg, t, stats + 0, stats + 128);
}

// stu pre-BN = elu( 0.5*( x@Wr + Hmean@W2 + meanY + b_st + [deg>0]*b2 ) )
__global__ __launch_bounds__(256, 3) void out_stu_h(
    const __half* __restrict__ meanY, const __half* __restrict__ x_stu,
    const __half* __restrict__ Hmean, const int* __restrict__ degP,
    const float* __restrict__ Wr, const float* __restrict__ W2,
    const float* __restrict__ b_st, const float* __restrict__ b2,
    float* __restrict__ out, float* __restrict__ stats, int M) {
    extern __shared__ __half smem_h[];
    __half* sA = smem_h;
    __half* sW = smem_h + TILE_M * SAH;
    int rowBase = blockIdx.x * TILE_M;
    float acc[2][4][4] = {};

    stage_A_hh(x_stu, M, rowBase, sA);
    stage_Wt_h(Wr, nullptr, sW);
    __syncthreads();
    mm_h32(sA, sW, acc);
    __syncthreads();
    stage_A_hh(Hmean, M, rowBase, sA);
    stage_Wt_h(W2, nullptr, sW);
    __syncthreads();
    mm_h32(sA, sW, acc);

    int lane = threadIdx.x & 31, w = threadIdx.x >> 5;
    int g = lane >> 2, t = lane & 3;
    int rg = w >> 2, cg = w & 3;
    float lsum[8] = {}, lss[8] = {};
#pragma unroll
    for (int mi = 0; mi < 2; mi++) {
        int rA = rowBase + rg * 32 + mi * 16 + g, rB = rA + 8;
        float hA = (rA < M && degP[rA] > 0) ? 1.f : 0.f;
        float hB = (rB < M && degP[rB] > 0) ? 1.f : 0.f;
#pragma unroll
        for (int j = 0; j < 4; j++) {
            int c = cg * 32 + j * 8 + 2 * t;
            float bs0 = b_st[c], bs1 = b_st[c + 1];
            float b20 = b2[c], b21 = b2[c + 1];
            if (rA < M) {
                float2 y = __half22float2(*(const __half2*)(meanY + (size_t)rA * D + c));
                float e0 = elu1(0.5f * (acc[mi][j][0] + y.x + bs0 + hA * b20));
                float e1 = elu1(0.5f * (acc[mi][j][1] + y.y + bs1 + hA * b21));
                *(float2*)(out + (size_t)rA * D + c) = make_float2(e0, e1);
                lsum[2 * j] += e0; lss[2 * j] += e0 * e0;
                lsum[2 * j + 1] += e1; lss[2 * j + 1] += e1 * e1;
            }
            if (rB < M) {
                float2 y = __half22float2(*(const __half2*)(meanY + (size_t)rB * D + c));
                float e2 = elu1(0.5f * (acc[mi][j][2] + y.x + bs0 + hB * b20));
                float e3 = elu1(0.5f * (acc[mi][j][3] + y.y + bs1 + hB * b21));
                *(float2*)(out + (size_t)rB * D + c) = make_float2(e2, e3);
                lsum[2 * j] += e2; lss[2 * j] += e2 * e2;
                lsum[2 * j + 1] += e3; lss[2 * j + 1] += e3 * e3;
            }
        }
    }
    stats_reduce((float*)sA, lsum, lss, cg, t, stats + 256, stats + 384);
}

// ---------------- batch-norm finalize -----------------------------------------
__global__ void bn_final_kernel(float* __restrict__ x,
                                const float* __restrict__ stats, int statOff,
                                const float* __restrict__ g,
                                const float* __restrict__ beta, int N) {
    __shared__ float sScale[128], sShift[128];
    if (threadIdx.x < 128) {
        int j = threadIdx.x;
        float invN = 1.f / (float)N;
        float mu = stats[statOff + j] * invN;
        float var = fmaxf(stats[statOff + 128 + j] * invN - mu * mu, 0.f);
        float sc = g[j] * rsqrtf(var + 1e-5f);
        sScale[j] = sc;
        sShift[j] = beta[j] - mu * sc;
    }
    __syncthreads();
    size_t total = (size_t)N * 32;
    size_t i = blockIdx.x * (size_t)blockDim.x + threadIdx.x;
    size_t stride = (size_t)gridDim.x * blockDim.x;
    float4* x4 = (float4*)x;
    for (; i < total; i += stride) {
        int j = ((int)i & 31) * 4;
        float4 v = x4[i];
        v.x = v.x * sScale[j + 0] + sShift[j + 0];
        v.y = v.y * sScale[j + 1] + sShift[j + 1];
        v.z = v.z * sScale[j + 2] + sShift[j + 2];
        v.w = v.w * sScale[j + 3] + sShift[j + 3];
        x4[i] = v;
    }
}

// ---------------- launch -------------------------------------------------------
extern "C" void kernel_launch(void* const* d_in, const int* in_sizes, int n_in,
                              void* d_out, int out_size) {
    const float* x_student = (const float*)d_in[0];
    const float* x_item = (const float*)d_in[1];
    const int* responds_src = (const int*)d_in[2];
    const int* responds_dst = (const int*)d_in[3];
    const int* preceeds_src = (const int*)d_in[4];
    const int* preceeds_dst = (const int*)d_in[5];
    const float* sage_it_Wl = (const float*)d_in[6];
    const float* sage_it_Wr = (const float*)d_in[7];
    const float* sage_it_b = (const float*)d_in[8];
    const float* sage_st_Wl = (const float*)d_in[9];
    const float* sage_st_Wr = (const float*)d_in[10];
    const float* sage_st_b = (const float*)d_in[11];
    const float* sc_W1 = (const float*)d_in[12];
    const float* sc_b1 = (const float*)d_in[13];
    const float* sc_W2 = (const float*)d_in[14];
    const float* sc_b2 = (const float*)d_in[15];
    const float* bn_item_g = (const float*)d_in[16];
    const float* bn_item_b = (const float*)d_in[17];
    const float* bn_stu_g = (const float*)d_in[18];
    const float* bn_stu_b = (const float*)d_in[19];

    int n_stu = in_sizes[0] / D;
    int n_item = in_sizes[1] / D;
    int e_r = in_sizes[2];
    int e_p = in_sizes[4];

    const int DYN_SMEM = (TILE_M + 128) * SAH * 2;  // 52224 B

    static cudaStream_t s1 = nullptr, s2 = nullptr;
    static cudaEvent_t eStart, eFill, eCvS, eY, eG, eAI, eAY, eJoin;
    if (s1 == nullptr) {
        cudaStreamCreateWithFlags(&s1, cudaStreamNonBlocking);
        cudaStreamCreateWithFlags(&s2, cudaStreamNonBlocking);
        cudaEventCreateWithFlags(&eStart, cudaEventDisableTiming);
        cudaEventCreateWithFlags(&eFill, cudaEventDisableTiming);
        cudaEventCreateWithFlags(&eCvS, cudaEventDisableTiming);
        cudaEventCreateWithFlags(&eY, cudaEventDisableTiming);
        cudaEventCreateWithFlags(&eG, cudaEventDisableTiming);
        cudaEventCreateWithFlags(&eAI, cudaEventDisableTiming);
        cudaEventCreateWithFlags(&eAY, cudaEventDisableTiming);
        cudaEventCreateWithFlags(&eJoin, cudaEventDisableTiming);
        cudaFuncSetAttribute(gemm_one_hh, cudaFuncAttributeMaxDynamicSharedMemorySize, DYN_SMEM);
        cudaFuncSetAttribute(gemm_rq_h, cudaFuncAttributeMaxDynamicSharedMemorySize, DYN_SMEM);
        cudaFuncSetAttribute(out_item_h, cudaFuncAttributeMaxDynamicSharedMemorySize, DYN_SMEM);
        cudaFuncSetAttribute(out_stu_h, cudaFuncAttributeMaxDynamicSharedMemorySize, DYN_SMEM);
    }

    void *pHxS, *pHxI, *pYh, *pMeanIh, *pMeanYh, *pHh, *pR, *pQ, *pStats;
    void *pRpItem, *pAdjItem, *pRpRs, *pAdjRs, *pRpP, *pAdjP, *pDegP;
    cudaGetSymbolAddress(&pHxS, g_hx_stu);
    cudaGetSymbolAddress(&pHxI, g_hx_item);
    cudaGetSymbolAddress(&pYh, g_Yh);
    cudaGetSymbolAddress(&pMeanIh, g_meanI_h);
    cudaGetSymbolAddress(&pMeanYh, g_meanY_h);
    cudaGetSymbolAddress(&pHh, g_Hmean_h);
    cudaGetSymbolAddress(&pR, g_R);
    cudaGetSymbolAddress(&pQ, g_Q);
    cudaGetSymbolAddress(&pStats, g_stats);
    cudaGetSymbolAddress(&pRpItem, g_rp_item);
    cudaGetSymbolAddress(&pAdjItem, g_adj_item);
    cudaGetSymbolAddress(&pRpRs, g_rp_rs);
    cudaGetSymbolAddress(&pAdjRs, g_adj_rs);
    cudaGetSymbolAddress(&pRpP, g_rp_p);
    cudaGetSymbolAddress(&pAdjP, g_adj_p);
    cudaGetSymbolAddress(&pDegP, g_deg_p);

    float* out = (float*)d_out;
    float* out_item = out;
    float* out_stu = out + (size_t)n_item * D;
    float* stats = (float*)pStats;

    int maxE = max(e_r, e_p);
    int gb_stu = (n_stu + TILE_M - 1) / TILE_M;
    int gb_item = (n_item + TILE_M - 1) / TILE_M;

    // ---- fork ----
    cudaEventRecord(eStart, 0);
    cudaStreamWaitEvent(s1, eStart, 0);
    cudaStreamWaitEvent(s2, eStart, 0);

    // s2: convert x_student to half (feeds aggI, rq, out_stu)
    f2h_kernel<<<2048, 256, 0, s2>>>(x_student, (__half*)pHxS, (size_t)n_stu * 32);
    cudaEventRecord(eCvS, s2);

    // s1: convert x_item, then Y projection (half out)
    f2h_kernel<<<512, 256, 0, s1>>>(x_item, (__half*)pHxI, (size_t)n_item * 32);
    gemm_one_hh<<<gb_item, 256, DYN_SMEM, s1>>>((const __half*)pHxI, sage_st_Wl,
                                                (__half*)pYh, n_item);
    cudaEventRecord(eY, s1);
    cudaStreamWaitEvent(s1, eCvS, 0);
    gemm_rq_h<<<gb_stu, 256, DYN_SMEM, s1>>>((const __half*)pHxS, sc_W1,
                                             (float*)pR, (float*)pQ, n_stu);
    cudaEventRecord(eG, s1);

    // s0: CSR build + item aggregation
    zero_small_kernel<<<256, 256>>>();
    hist_kernel<<<(maxE + 255) / 256, 256>>>(responds_src, responds_dst, e_r,
                                             preceeds_dst, e_p);
    scan3_kernel<<<3, 1024>>>(n_item, n_stu);
    fill_kernel<<<(maxE + 255) / 256, 256>>>(responds_src, responds_dst, e_r,
                                             preceeds_src, preceeds_dst, e_p);
    cudaEventRecord(eFill, 0);
    cudaStreamWaitEvent(0, eCvS, 0);
    agg_gather_h<<<(n_item * 32 + 255) / 256, 256>>>(
        (const __half*)pHxS, (const int*)pRpItem, (const int*)pAdjItem,
        (__half*)pMeanIh, n_item);
    cudaEventRecord(eAI, 0);

    // s2: student SAGE aggregation (needs Yh + CSR)
    cudaStreamWaitEvent(s2, eY, 0);
    cudaStreamWaitEvent(s2, eFill, 0);
    agg_gather_h<<<(n_stu * 32 + 255) / 256, 256, 0, s2>>>(
        (const __half*)pYh, (const int*)pRpRs, (const int*)pAdjRs,
        (__half*)pMeanYh, n_stu);
    cudaEventRecord(eAY, s2);

    // s1: item output path
    cudaStreamWaitEvent(s1, eAI, 0);
    out_item_h<<<gb_item, 256, DYN_SMEM, s1>>>((const __half*)pMeanIh,
                                               (const __half*)pHxI,
                                               sage_it_Wl, sage_it_Wr, sage_it_b,
                                               out_item, stats, n_item);
    bn_final_kernel<<<512, 256, 0, s1>>>(out_item, stats, 0, bn_item_g, bn_item_b, n_item);
    cudaEventRecord(eJoin, s1);

    // s0: student path
    cudaStreamWaitEvent(0, eG, 0);
    simple_gather_kernel<<<(n_stu * 32 + 255) / 256, 256>>>(
        (const float*)pR, (const float*)pQ, sc_b1, (const int*)pRpP,
        (const int*)pAdjP, (__half*)pHh, n_stu);
    cudaStreamWaitEvent(0, eAY, 0);
    out_stu_h<<<gb_stu, 256, DYN_SMEM>>>((const __half*)pMeanYh,
                                         (const __half*)pHxS,
                                         (const __half*)pHh, (const int*)pDegP,
                                         sage_st_Wr, sc_W2, sage_st_b, sc_b2,
                                         out_stu, stats, n_stu);
    bn_final_kernel<<<2048, 256>>>(out_stu, stats, 256, bn_stu_g, bn_stu_b, n_stu);

    // ---- join ----
    cudaStreamWaitEvent(0, eJoin, 0);
}

// round 11
// speedup vs baseline: 1.5907x; 1.5907x over previous
#include <cuda_runtime.h>
#include <cuda_fp16.h>
#include <math.h>

#define D 128
#define MAX_N_STU 100000
#define MAX_N_ITEM 20000
#define MAX_E_R 500000
#define MAX_E_P 300000
#define SAH 136    // half stride: 272B rows -> conflict-free fragment LDS
#define TILE_M 64  // A-tile rows per block

// ---------------- scratch ------------------------------------------------------
__device__ __half g_hx_stu[(size_t)MAX_N_STU * D];
__device__ __half g_hx_item[(size_t)MAX_N_ITEM * D];
__device__ __half g_Yh[(size_t)MAX_N_ITEM * D];
__device__ __half g_XiWr_h[(size_t)MAX_N_ITEM * D];
__device__ __half g_XWr_h[(size_t)MAX_N_STU * D];
__device__ __half g_meanI_h[(size_t)MAX_N_ITEM * D];
__device__ __half g_meanY_h[(size_t)MAX_N_STU * D];
__device__ __half g_Hmean_h[(size_t)MAX_N_STU * D];
__device__ float g_R[(size_t)MAX_N_STU * D];
__device__ float g_Q[(size_t)MAX_N_STU * D];
__device__ float g_stats[4 * D];

// CSR scratch
__device__ int g_deg_item[MAX_N_ITEM];
__device__ int g_rp_item[MAX_N_ITEM + 1];
__device__ int g_cur_item[MAX_N_ITEM];
__device__ int g_adj_item[MAX_E_R];
__device__ int g_deg_rs[MAX_N_STU];
__device__ int g_rp_rs[MAX_N_STU + 1];
__device__ int g_cur_rs[MAX_N_STU];
__device__ int g_adj_rs[MAX_E_R];
__device__ int g_deg_p[MAX_N_STU];
__device__ int g_rp_p[MAX_N_STU + 1];
__device__ int g_cur_p[MAX_N_STU];
__device__ int g_adj_p[MAX_E_P];

// ---------------- fp32 -> fp16 convert ----------------------------------------
__global__ void f2h_kernel(const float* __restrict__ X, __half* __restrict__ H,
                           size_t n4) {
    size_t i = blockIdx.x * (size_t)blockDim.x + threadIdx.x;
    size_t stride = (size_t)gridDim.x * blockDim.x;
    for (; i < n4; i += stride) {
        float4 v = ((const float4*)X)[i];
        __half2* p = (__half2*)H + 2 * i;
        p[0] = __floats2half2_rn(v.x, v.y);
        p[1] = __floats2half2_rn(v.z, v.w);
    }
}

// ---------------- small zero ---------------------------------------------------
__global__ void zero_small_kernel() {
    int i = blockIdx.x * blockDim.x + threadIdx.x;
    int stride = gridDim.x * blockDim.x;
    for (int x = i; x < MAX_N_STU; x += stride) {
        g_deg_rs[x] = 0;
        g_deg_p[x] = 0;
        if (x < MAX_N_ITEM) g_deg_item[x] = 0;
        if (x < 4 * D) g_stats[x] = 0.f;
    }
}

// ---------------- CSR build ----------------------------------------------------
__global__ void hist_kernel(const int* __restrict__ rsrc, const int* __restrict__ rdst,
                            int eR, const int* __restrict__ pdst, int eP) {
    int i = blockIdx.x * blockDim.x + threadIdx.x;
    if (i < eR) {
        atomicAdd(&g_deg_item[rdst[i]], 1);
        atomicAdd(&g_deg_rs[rsrc[i]], 1);
    }
    if (i < eP) atomicAdd(&g_deg_p[pdst[i]], 1);
}

__global__ __launch_bounds__(1024) void scan3_kernel(int n_item, int n_stu) {
    int n;
    int *deg, *rp, *cur;
    if (blockIdx.x == 0) { n = n_item; deg = g_deg_item; rp = g_rp_item; cur = g_cur_item; }
    else if (blockIdx.x == 1) { n = n_stu; deg = g_deg_rs; rp = g_rp_rs; cur = g_cur_rs; }
    else { n = n_stu; deg = g_deg_p; rp = g_rp_p; cur = g_cur_p; }

    __shared__ int warpSums[32];
    int chunk = (n + 1023) >> 10;
    int begin = min((int)threadIdx.x * chunk, n);
    int end = min(begin + chunk, n);
    int s = 0;
    for (int i = begin; i < end; i++) s += deg[i];
    int lane = threadIdx.x & 31, w = threadIdx.x >> 5;
    int v = s;
#pragma unroll
    for (int o = 1; o < 32; o <<= 1) {
        int t = __shfl_up_sync(0xffffffffu, v, o);
        if (lane >= o) v += t;
    }
    if (lane == 31) warpSums[w] = v;
    __syncthreads();
    if (w == 0) {
        int t = warpSums[lane];
#pragma unroll
        for (int o = 1; o < 32; o <<= 1) {
            int u = __shfl_up_sync(0xffffffffu, t, o);
            if (lane >= o) t += u;
        }
        warpSums[lane] = t;
    }
    __syncthreads();
    int excl = v - s + (w > 0 ? warpSums[w - 1] : 0);
    int run = excl;
    for (int i = begin; i < end; i++) {
        rp[i] = run;
        cur[i] = run;
        run += deg[i];
    }
    if (begin < n && end == n) rp[n] = run;
}

__global__ void fill_kernel(const int* __restrict__ rsrc, const int* __restrict__ rdst,
                            int eR, const int* __restrict__ psrc,
                            const int* __restrict__ pdst, int eP) {
    int i = blockIdx.x * blockDim.x + threadIdx.x;
    if (i < eR) {
        int s = rsrc[i], d = rdst[i];
        g_adj_item[atomicAdd(&g_cur_item[d], 1)] = s;
        g_adj_rs[atomicAdd(&g_cur_rs[s], 1)] = d;
    }
    if (i < eP) {
        g_adj_p[atomicAdd(&g_cur_p[pdst[i]], 1)] = psrc[i];
    }
}

// ---------------- CSR gather (half features, warp/node, 8-way MLP) -------------
__device__ __forceinline__ float2 u2f2(unsigned u) {
    return __half22float2(*(__half2*)&u);
}

__global__ void agg_gather_h(const __half* __restrict__ X,
                             const int* __restrict__ rp,
                             const int* __restrict__ adj,
                             __half* __restrict__ out, int N) {
    int node = (blockIdx.x * blockDim.x + threadIdx.x) >> 5;
    if (node >= N) return;
    int lane = threadIdx.x & 31;
    int b = rp[node], e = rp[node + 1];
    float a0 = 0.f, a1 = 0.f, a2 = 0.f, a3 = 0.f;
    int i = b;
    for (; i + 8 <= e; i += 8) {
        uint2 v[8];
#pragma unroll
        for (int j = 0; j < 8; j++) {
            int n = __ldg(adj + i + j);
            v[j] = ((const uint2*)(X + (size_t)n * D))[lane];
        }
#pragma unroll
        for (int j = 0; j < 8; j++) {
            float2 p = u2f2(v[j].x), q = u2f2(v[j].y);
            a0 += p.x; a1 += p.y; a2 += q.x; a3 += q.y;
        }
    }
    for (; i < e; i++) {
        int n = __ldg(adj + i);
        uint2 v = ((const uint2*)(X + (size_t)n * D))[lane];
        float2 p = u2f2(v.x), q = u2f2(v.y);
        a0 += p.x; a1 += p.y; a2 += q.x; a3 += q.y;
    }
    float inv = 1.f / (float)max(e - b, 1);
    __half2* o = (__half2*)(out + (size_t)node * D) + 2 * lane;
    o[0] = __floats2half2_rn(a0 * inv, a1 * inv);
    o[1] = __floats2half2_rn(a2 * inv, a3 * inv);
}

__device__ __forceinline__ float elu1(float x) {
    return x > 0.f ? x : expm1f(x);
}

// Hmean[d] = mean_s elu(R[s] + Q[d] + b1)   (fp32 R/Q in, half out)
__global__ void simple_gather_kernel(const float* __restrict__ R,
                                     const float* __restrict__ Q,
                                     const float* __restrict__ b1,
                                     const int* __restrict__ rp,
                                     const int* __restrict__ adj,
                                     __half* __restrict__ Hmean, int N) {
    int node = (blockIdx.x * blockDim.x + threadIdx.x) >> 5;
    if (node >= N) return;
    int lane = threadIdx.x & 31;
    int b = rp[node], e = rp[node + 1];
    float4 qd = ((const float4*)(Q + (size_t)node * D))[lane];
    float4 bb = ((const float4*)b1)[lane];
    qd.x += bb.x; qd.y += bb.y; qd.z += bb.z; qd.w += bb.w;
    float4 acc = make_float4(0.f, 0.f, 0.f, 0.f);
    int i = b;
    for (; i + 4 <= e; i += 4) {
        int n0 = __ldg(adj + i), n1 = __ldg(adj + i + 1);
        int n2 = __ldg(adj + i + 2), n3 = __ldg(adj + i + 3);
        float4 v0 = ((const float4*)(R + (size_t)n0 * D))[lane];
        float4 v1 = ((const float4*)(R + (size_t)n1 * D))[lane];
        float4 v2 = ((const float4*)(R + (size_t)n2 * D))[lane];
        float4 v3 = ((const float4*)(R + (size_t)n3 * D))[lane];
        acc.x += elu1(v0.x + qd.x) + elu1(v1.x + qd.x) + elu1(v2.x + qd.x) + elu1(v3.x + qd.x);
        acc.y += elu1(v0.y + qd.y) + elu1(v1.y + qd.y) + elu1(v2.y + qd.y) + elu1(v3.y + qd.y);
        acc.z += elu1(v0.z + qd.z) + elu1(v1.z + qd.z) + elu1(v2.z + qd.z) + elu1(v3.z + qd.z);
        acc.w += elu1(v0.w + qd.w) + elu1(v1.w + qd.w) + elu1(v2.w + qd.w) + elu1(v3.w + qd.w);
    }
    for (; i < e; i++) {
        int n = __ldg(adj + i);
        float4 v = ((const float4*)(R + (size_t)n * D))[lane];
        acc.x += elu1(v.x + qd.x);
        acc.y += elu1(v.y + qd.y);
        acc.z += elu1(v.z + qd.z);
        acc.w += elu1(v.w + qd.w);
    }
    float inv = 1.f / (float)max(e - b, 1);
    __half2* o = (__half2*)(Hmean + (size_t)node * D) + 2 * lane;
    o[0] = __floats2half2_rn(acc.x * inv, acc.y * inv);
    o[1] = __floats2half2_rn(acc.z * inv, acc.w * inv);
}

// ---------------- fp16 tensor-core GEMM pieces ---------------------------------
__device__ __forceinline__ void stage_A_hh(const __half* __restrict__ A, int M,
                                           int rowBase, __half* sA) {
    for (int i = threadIdx.x; i < TILE_M * 32; i += 256) {
        int r = i >> 5, c = i & 31;
        int gr = rowBase + r;
        uint2 v = make_uint2(0u, 0u);
        if (gr < M) v = ((const uint2*)(A + (size_t)gr * D))[c];
        *(uint2*)(sA + r * SAH + c * 4) = v;
    }
}

__device__ __forceinline__ void stage_Wt_h(const float* __restrict__ W,
                                           const float* __restrict__ Wb,
                                           __half* sWt) {
    for (int i = threadIdx.x; i < 128 * 32; i += 256) {
        int k = i & 127, n4 = i >> 7;
        float4 v = ((const float4*)(W + (size_t)k * D))[n4];
        if (Wb) {
            float4 b = ((const float4*)(Wb + (size_t)k * D))[n4];
            v.x -= b.x; v.y -= b.y; v.z -= b.z; v.w -= b.w;
        }
        sWt[(n4 * 4 + 0) * SAH + k] = __float2half_rn(v.x);
        sWt[(n4 * 4 + 1) * SAH + k] = __float2half_rn(v.y);
        sWt[(n4 * 4 + 2) * SAH + k] = __float2half_rn(v.z);
        sWt[(n4 * 4 + 3) * SAH + k] = __float2half_rn(v.w);
    }
}

// m32n32 warp tile via mma.m16n8k16 f16->f32 (scalar LDS fragments — proven fastest).
__device__ __forceinline__ void mm_h32(const __half* sA, const __half* sWt,
                                       float acc[2][4][4]) {
    int lane = threadIdx.x & 31, w = threadIdx.x >> 5;
    int g = lane >> 2, t = lane & 3;
    int rg = w >> 2, cg = w & 3;
#pragma unroll
    for (int k0 = 0; k0 < 128; k0 += 16) {
        unsigned a[2][4];
#pragma unroll
        for (int mi = 0; mi < 2; mi++) {
            const __half* Ab = sA + (rg * 32 + mi * 16 + g) * SAH + k0 + 2 * t;
            a[mi][0] = *(const unsigned*)Ab;
            a[mi][1] = *(const unsigned*)(Ab + 8 * SAH);
            a[mi][2] = *(const unsigned*)(Ab + 8);
            a[mi][3] = *(const unsigned*)(Ab + 8 * SAH + 8);
        }
#pragma unroll
        for (int j = 0; j < 4; j++) {
            const __half* Bb = sWt + (cg * 32 + j * 8 + g) * SAH + k0 + 2 * t;
            unsigned b0 = *(const unsigned*)Bb;
            unsigned b1 = *(const unsigned*)(Bb + 8);
#pragma unroll
            for (int mi = 0; mi < 2; mi++) {
                asm volatile(
                    "mma.sync.aligned.m16n8k16.row.col.f32.f16.f16.f32 "
                    "{%0,%1,%2,%3},{%4,%5,%6,%7},{%8,%9},{%0,%1,%2,%3};"
                    : "+f"(acc[mi][j][0]), "+f"(acc[mi][j][1]),
                      "+f"(acc[mi][j][2]), "+f"(acc[mi][j][3])
                    : "r"(a[mi][0]), "r"(a[mi][1]), "r"(a[mi][2]), "r"(a[mi][3]),
                      "r"(b0), "r"(b1));
            }
        }
    }
}

__device__ __forceinline__ void store_tile_f(float* __restrict__ C, int M, int rowBase,
                                             float acc[2][4][4]) {
    int lane = threadIdx.x & 31, w = threadIdx.x >> 5;
    int g = lane >> 2, t = lane & 3;
    int rg = w >> 2, cg = w & 3;
#pragma unroll
    for (int mi = 0; mi < 2; mi++) {
        int rA = rowBase + rg * 32 + mi * 16 + g, rB = rA + 8;
#pragma unroll
        for (int j = 0; j < 4; j++) {
            int c = cg * 32 + j * 8 + 2 * t;
            if (rA < M) *(float2*)(C + (size_t)rA * D + c) = make_float2(acc[mi][j][0], acc[mi][j][1]);
            if (rB < M) *(float2*)(C + (size_t)rB * D + c) = make_float2(acc[mi][j][2], acc[mi][j][3]);
        }
    }
}

__device__ __forceinline__ void store_tile_h(__half* __restrict__ C, int M, int rowBase,
                                             float acc[2][4][4]) {
    int lane = threadIdx.x & 31, w = threadIdx.x >> 5;
    int g = lane >> 2, t = lane & 3;
    int rg = w >> 2, cg = w & 3;
#pragma unroll
    for (int mi = 0; mi < 2; mi++) {
        int rA = rowBase + rg * 32 + mi * 16 + g, rB = rA + 8;
#pragma unroll
        for (int j = 0; j < 4; j++) {
            int c = cg * 32 + j * 8 + 2 * t;
            if (rA < M) *(__half2*)(C + (size_t)rA * D + c) = __floats2half2_rn(acc[mi][j][0], acc[mi][j][1]);
            if (rB < M) *(__half2*)(C + (size_t)rB * D + c) = __floats2half2_rn(acc[mi][j][2], acc[mi][j][3]);
        }
    }
}

// C = A @ W (half in, half out)
__global__ __launch_bounds__(256, 3) void gemm_one_hh(const __half* __restrict__ A,
                                                      const float* __restrict__ W,
                                                      __half* __restrict__ C, int M) {
    extern __shared__ __half smem_h[];
    __half* sA = smem_h;
    __half* sW = smem_h + TILE_M * SAH;
    int rowBase = blockIdx.x * TILE_M;
    float acc[2][4][4] = {};
    stage_A_hh(A, M, rowBase, sA);
    stage_Wt_h(W, nullptr, sW);
    __syncthreads();
    mm_h32(sA, sW, acc);
    store_tile_h(C, M, rowBase, acc);
}

// Q = x@W1bot (f32), R = x@(W1top-W1bot) (f32), XWr = x@Wr (half). A staged once.
__global__ __launch_bounds__(256, 3) void gemm_rqw_h(const __half* __restrict__ x,
                                                     const float* __restrict__ W1,
                                                     const float* __restrict__ Wr,
                                                     float* __restrict__ Rm,
                                                     float* __restrict__ Qm,
                                                     __half* __restrict__ XWr, int M) {
    extern __shared__ __half smem_h[];
    __half* sA = smem_h;
    __half* sW = smem_h + TILE_M * SAH;
    int rowBase = blockIdx.x * TILE_M;

    stage_A_hh(x, M, rowBase, sA);
    stage_Wt_h(W1 + 128 * D, nullptr, sW);
    __syncthreads();
    {
        float acc[2][4][4] = {};
        mm_h32(sA, sW, acc);
        store_tile_f(Qm, M, rowBase, acc);
    }
    __syncthreads();
    stage_Wt_h(W1, W1 + 128 * D, sW);
    __syncthreads();
    {
        float acc[2][4][4] = {};
        mm_h32(sA, sW, acc);
        store_tile_f(Rm, M, rowBase, acc);
    }
    __syncthreads();
    stage_Wt_h(Wr, nullptr, sW);
    __syncthreads();
    {
        float acc[2][4][4] = {};
        mm_h32(sA, sW, acc);
        store_tile_h(XWr, M, rowBase, acc);
    }
}

// smem + global reduction of per-column sums.
__device__ __forceinline__ void stats_reduce(float* sred, const float lsum[8],
                                             const float lss[8], int cg, int t,
                                             float* __restrict__ statSum,
                                             float* __restrict__ statSS) {
    __syncthreads();
    sred[threadIdx.x] = 0.f;
    __syncthreads();
#pragma unroll
    for (int j = 0; j < 4; j++) {
        int c = cg * 32 + j * 8 + 2 * t;
        atomicAdd(&sred[c], lsum[2 * j]);
        atomicAdd(&sred[c + 1], lsum[2 * j + 1]);
        atomicAdd(&sred[128 + c], lss[2 * j]);
        atomicAdd(&sred[128 + c + 1], lss[2 * j + 1]);
    }
    __syncthreads();
    if (threadIdx.x < 128) {
        atomicAdd(statSum + threadIdx.x, sred[threadIdx.x]);
        atomicAdd(statSS + threadIdx.x, sred[128 + threadIdx.x]);
    }
}

// item pre-BN = elu( meanI@Wl + XiWr + b ) -> out fp32, + BN stats (SINGLE mm)
__global__ __launch_bounds__(256, 3) void out_item_h(
    const __half* __restrict__ meanI, const __half* __restrict__ XiWr,
    const float* __restrict__ Wl, const float* __restrict__ b,
    float* __restrict__ out, float* __restrict__ stats, int M) {
    extern __shared__ __half smem_h[];
    __half* sA = smem_h;
    __half* sW = smem_h + TILE_M * SAH;
    int rowBase = blockIdx.x * TILE_M;
    float acc[2][4][4] = {};

    stage_A_hh(meanI, M, rowBase, sA);
    stage_Wt_h(Wl, nullptr, sW);
    __syncthreads();
    mm_h32(sA, sW, acc);

    int lane = threadIdx.x & 31, w = threadIdx.x >> 5;
    int g = lane >> 2, t = lane & 3;
    int rg = w >> 2, cg = w & 3;
    float lsum[8] = {}, lss[8] = {};
#pragma unroll
    for (int mi = 0; mi < 2; mi++) {
        int rA = rowBase + rg * 32 + mi * 16 + g, rB = rA + 8;
#pragma unroll
        for (int j = 0; j < 4; j++) {
            int c = cg * 32 + j * 8 + 2 * t;
            float b0v = b[c], b1v = b[c + 1];
            if (rA < M) {
                float2 xw = __half22float2(*(const __half2*)(XiWr + (size_t)rA * D + c));
                float e0 = elu1(acc[mi][j][0] + xw.x + b0v);
                float e1 = elu1(acc[mi][j][1] + xw.y + b1v);
                *(float2*)(out + (size_t)rA * D + c) = make_float2(e0, e1);
                lsum[2 * j] += e0; lss[2 * j] += e0 * e0;
                lsum[2 * j + 1] += e1; lss[2 * j + 1] += e1 * e1;
            }
            if (rB < M) {
                float2 xw = __half22float2(*(const __half2*)(XiWr + (size_t)rB * D + c));
                float e2 = elu1(acc[mi][j][2] + xw.x + b0v);
                float e3 = elu1(acc[mi][j][3] + xw.y + b1v);
                *(float2*)(out + (size_t)rB * D + c) = make_float2(e2, e3);
                lsum[2 * j] += e2; lss[2 * j] += e2 * e2;
                lsum[2 * j + 1] += e3; lss[2 * j + 1] += e3 * e3;
            }
        }
    }
    stats_reduce((float*)sA, lsum, lss, cg, t, stats + 0, stats + 128);
}

// stu pre-BN = elu( 0.5*( Hmean@W2 + XWr + meanY + b_st + [deg>0]*b2 ) ) (SINGLE mm)
__global__ __launch_bounds__(256, 3) void out_stu_h(
    const __half* __restrict__ Hmean, const __half* __restrict__ XWr,
    const __half* __restrict__ meanY, const int* __restrict__ degP,
    const float* __restrict__ W2, const float* __restrict__ b_st,
    const float* __restrict__ b2, float* __restrict__ out,
    float* __restrict__ stats, int M) {
    extern __shared__ __half smem_h[];
    __half* sA = smem_h;
    __half* sW = smem_h + TILE_M * SAH;
    int rowBase = blockIdx.x * TILE_M;
    float acc[2][4][4] = {};

    stage_A_hh(Hmean, M, rowBase, sA);
    stage_Wt_h(W2, nullptr, sW);
    __syncthreads();
    mm_h32(sA, sW, acc);

    int lane = threadIdx.x & 31, w = threadIdx.x >> 5;
    int g = lane >> 2, t = lane & 3;
    int rg = w >> 2, cg = w & 3;
    float lsum[8] = {}, lss[8] = {};
#pragma unroll
    for (int mi = 0; mi < 2; mi++) {
        int rA = rowBase + rg * 32 + mi * 16 + g, rB = rA + 8;
        float hA = (rA < M && degP[rA] > 0) ? 1.f : 0.f;
        float hB = (rB < M && degP[rB] > 0) ? 1.f : 0.f;
#pragma unroll
        for (int j = 0; j < 4; j++) {
            int c = cg * 32 + j * 8 + 2 * t;
            float bs0 = b_st[c], bs1 = b_st[c + 1];
            float b20 = b2[c], b21 = b2[c + 1];
            if (rA < M) {
                float2 y = __half22float2(*(const __half2*)(meanY + (size_t)rA * D + c));
                float2 xw = __half22float2(*(const __half2*)(XWr + (size_t)rA * D + c));
                float e0 = elu1(0.5f * (acc[mi][j][0] + xw.x + y.x + bs0 + hA * b20));
                float e1 = elu1(0.5f * (acc[mi][j][1] + xw.y + y.y + bs1 + hA * b21));
                *(float2*)(out + (size_t)rA * D + c) = make_float2(e0, e1);
                lsum[2 * j] += e0; lss[2 * j] += e0 * e0;
                lsum[2 * j + 1] += e1; lss[2 * j + 1] += e1 * e1;
            }
            if (rB < M) {
                float2 y = __half22float2(*(const __half2*)(meanY + (size_t)rB * D + c));
                float2 xw = __half22float2(*(const __half2*)(XWr + (size_t)rB * D + c));
                float e2 = elu1(0.5f * (acc[mi][j][2] + xw.x + y.x + bs0 + hB * b20));
                float e3 = elu1(0.5f * (acc[mi][j][3] + xw.y + y.y + bs1 + hB * b21));
                *(float2*)(out + (size_t)rB * D + c) = make_float2(e2, e3);
                lsum[2 * j] += e2; lss[2 * j] += e2 * e2;
                lsum[2 * j + 1] += e3; lss[2 * j + 1] += e3 * e3;
            }
        }
    }
    stats_reduce((float*)sA, lsum, lss, cg, t, stats + 256, stats + 384);
}

// ---------------- batch-norm finalize -----------------------------------------
__global__ void bn_final_kernel(float* __restrict__ x,
                                const float* __restrict__ stats, int statOff,
                                const float* __restrict__ g,
                                const float* __restrict__ beta, int N) {
    __shared__ float sScale[128], sShift[128];
    if (threadIdx.x < 128) {
        int j = threadIdx.x;
        float invN = 1.f / (float)N;
        float mu = stats[statOff + j] * invN;
        float var = fmaxf(stats[statOff + 128 + j] * invN - mu * mu, 0.f);
        float sc = g[j] * rsqrtf(var + 1e-5f);
        sScale[j] = sc;
        sShift[j] = beta[j] - mu * sc;
    }
    __syncthreads();
    size_t total = (size_t)N * 32;
    size_t i = blockIdx.x * (size_t)blockDim.x + threadIdx.x;
    size_t stride = (size_t)gridDim.x * blockDim.x;
    float4* x4 = (float4*)x;
    for (; i < total; i += stride) {
        int j = ((int)i & 31) * 4;
        float4 v = x4[i];
        v.x = v.x * sScale[j + 0] + sShift[j + 0];
        v.y = v.y * sScale[j + 1] + sShift[j + 1];
        v.z = v.z * sScale[j + 2] + sShift[j + 2];
        v.w = v.w * sScale[j + 3] + sShift[j + 3];
        x4[i] = v;
    }
}

// ---------------- launch -------------------------------------------------------
extern "C" void kernel_launch(void* const* d_in, const int* in_sizes, int n_in,
                              void* d_out, int out_size) {
    const float* x_student = (const float*)d_in[0];
    const float* x_item = (const float*)d_in[1];
    const int* responds_src = (const int*)d_in[2];
    const int* responds_dst = (const int*)d_in[3];
    const int* preceeds_src = (const int*)d_in[4];
    const int* preceeds_dst = (const int*)d_in[5];
    const float* sage_it_Wl = (const float*)d_in[6];
    const float* sage_it_Wr = (const float*)d_in[7];
    const float* sage_it_b = (const float*)d_in[8];
    const float* sage_st_Wl = (const float*)d_in[9];
    const float* sage_st_Wr = (const float*)d_in[10];
    const float* sage_st_b = (const float*)d_in[11];
    const float* sc_W1 = (const float*)d_in[12];
    const float* sc_b1 = (const float*)d_in[13];
    const float* sc_W2 = (const float*)d_in[14];
    const float* sc_b2 = (const float*)d_in[15];
    const float* bn_item_g = (const float*)d_in[16];
    const float* bn_item_b = (const float*)d_in[17];
    const float* bn_stu_g = (const float*)d_in[18];
    const float* bn_stu_b = (const float*)d_in[19];

    int n_stu = in_sizes[0] / D;
    int n_item = in_sizes[1] / D;
    int e_r = in_sizes[2];
    int e_p = in_sizes[4];

    const int DYN_SMEM = (TILE_M + 128) * SAH * 2;  // 52224 B

    static cudaStream_t s1 = nullptr, s2 = nullptr;
    static cudaEvent_t eStart, eFill, eCvS, eY, eG, eAI, eAY, eJoin;
    if (s1 == nullptr) {
        cudaStreamCreateWithFlags(&s1, cudaStreamNonBlocking);
        cudaStreamCreateWithFlags(&s2, cudaStreamNonBlocking);
        cudaEventCreateWithFlags(&eStart, cudaEventDisableTiming);
        cudaEventCreateWithFlags(&eFill, cudaEventDisableTiming);
        cudaEventCreateWithFlags(&eCvS, cudaEventDisableTiming);
        cudaEventCreateWithFlags(&eY, cudaEventDisableTiming);
        cudaEventCreateWithFlags(&eG, cudaEventDisableTiming);
        cudaEventCreateWithFlags(&eAI, cudaEventDisableTiming);
        cudaEventCreateWithFlags(&eAY, cudaEventDisableTiming);
        cudaEventCreateWithFlags(&eJoin, cudaEventDisableTiming);
        cudaFuncSetAttribute(gemm_one_hh, cudaFuncAttributeMaxDynamicSharedMemorySize, DYN_SMEM);
        cudaFuncSetAttribute(gemm_rqw_h, cudaFuncAttributeMaxDynamicSharedMemorySize, DYN_SMEM);
        cudaFuncSetAttribute(out_item_h, cudaFuncAttributeMaxDynamicSharedMemorySize, DYN_SMEM);
        cudaFuncSetAttribute(out_stu_h, cudaFuncAttributeMaxDynamicSharedMemorySize, DYN_SMEM);
    }

    void *pHxS, *pHxI, *pYh, *pXiWr, *pXWr, *pMeanIh, *pMeanYh, *pHh, *pR, *pQ, *pStats;
    void *pRpItem, *pAdjItem, *pRpRs, *pAdjRs, *pRpP, *pAdjP, *pDegP;
    cudaGetSymbolAddress(&pHxS, g_hx_stu);
    cudaGetSymbolAddress(&pHxI, g_hx_item);
    cudaGetSymbolAddress(&pYh, g_Yh);
    cudaGetSymbolAddress(&pXiWr, g_XiWr_h);
    cudaGetSymbolAddress(&pXWr, g_XWr_h);
    cudaGetSymbolAddress(&pMeanIh, g_meanI_h);
    cudaGetSymbolAddress(&pMeanYh, g_meanY_h);
    cudaGetSymbolAddress(&pHh, g_Hmean_h);
    cudaGetSymbolAddress(&pR, g_R);
    cudaGetSymbolAddress(&pQ, g_Q);
    cudaGetSymbolAddress(&pStats, g_stats);
    cudaGetSymbolAddress(&pRpItem, g_rp_item);
    cudaGetSymbolAddress(&pAdjItem, g_adj_item);
    cudaGetSymbolAddress(&pRpRs, g_rp_rs);
    cudaGetSymbolAddress(&pAdjRs, g_adj_rs);
    cudaGetSymbolAddress(&pRpP, g_rp_p);
    cudaGetSymbolAddress(&pAdjP, g_adj_p);
    cudaGetSymbolAddress(&pDegP, g_deg_p);

    float* out = (float*)d_out;
    float* out_item = out;
    float* out_stu = out + (size_t)n_item * D;
    float* stats = (float*)pStats;

    int maxE = max(e_r, e_p);
    int gb_stu = (n_stu + TILE_M - 1) / TILE_M;
    int gb_item = (n_item + TILE_M - 1) / TILE_M;

    // ---- fork ----
    cudaEventRecord(eStart, 0);
    cudaStreamWaitEvent(s1, eStart, 0);
    cudaStreamWaitEvent(s2, eStart, 0);

    // s2: convert x_student to half
    f2h_kernel<<<2048, 256, 0, s2>>>(x_student, (__half*)pHxS, (size_t)n_stu * 32);
    cudaEventRecord(eCvS, s2);

    // s1: convert x_item, then Y and XiWr projections (20k rows each)
    f2h_kernel<<<512, 256, 0, s1>>>(x_item, (__half*)pHxI, (size_t)n_item * 32);
    gemm_one_hh<<<gb_item, 256, DYN_SMEM, s1>>>((const __half*)pHxI, sage_st_Wl,
                                                (__half*)pYh, n_item);
    cudaEventRecord(eY, s1);
    gemm_one_hh<<<gb_item, 256, DYN_SMEM, s1>>>((const __half*)pHxI, sage_it_Wr,
                                                (__half*)pXiWr, n_item);
    cudaStreamWaitEvent(s1, eCvS, 0);
    // s1: Q/R/XWr projections (A staged once, 3 mms)
    gemm_rqw_h<<<gb_stu, 256, DYN_SMEM, s1>>>((const __half*)pHxS, sc_W1, sage_st_Wr,
                                              (float*)pR, (float*)pQ, (__half*)pXWr,
                                              n_stu);
    cudaEventRecord(eG, s1);

    // s0: CSR build + item aggregation
    zero_small_kernel<<<256, 256>>>();
    hist_kernel<<<(maxE + 255) / 256, 256>>>(responds_src, responds_dst, e_r,
                                             preceeds_dst, e_p);
    scan3_kernel<<<3, 1024>>>(n_item, n_stu);
    fill_kernel<<<(maxE + 255) / 256, 256>>>(responds_src, responds_dst, e_r,
                                             preceeds_src, preceeds_dst, e_p);
    cudaEventRecord(eFill, 0);
    cudaStreamWaitEvent(0, eCvS, 0);
    agg_gather_h<<<(n_item * 32 + 255) / 256, 256>>>(
        (const __half*)pHxS, (const int*)pRpItem, (const int*)pAdjItem,
        (__half*)pMeanIh, n_item);
    cudaEventRecord(eAI, 0);

    // s2: student SAGE aggregation (needs Yh + CSR)
    cudaStreamWaitEvent(s2, eY, 0);
    cudaStreamWaitEvent(s2, eFill, 0);
    agg_gather_h<<<(n_stu * 32 + 255) / 256, 256, 0, s2>>>(
        (const __half*)pYh, (const int*)pRpRs, (const int*)pAdjRs,
        (__half*)pMeanYh, n_stu);
    cudaEventRecord(eAY, s2);

    // s1: item output path (single mm; XiWr already on s1)
    cudaStreamWaitEvent(s1, eAI, 0);
    out_item_h<<<gb_item, 256, DYN_SMEM, s1>>>((const __half*)pMeanIh,
                                               (const __half*)pXiWr,
                                               sage_it_Wl, sage_it_b,
                                               out_item, stats, n_item);
    bn_final_kernel<<<512, 256, 0, s1>>>(out_item, stats, 0, bn_item_g, bn_item_b, n_item);
    cudaEventRecord(eJoin, s1);

    // s0: student path (single-mm out_stu)
    cudaStreamWaitEvent(0, eG, 0);
    simple_gather_kernel<<<(n_stu * 32 + 255) / 256, 256>>>(
        (const float*)pR, (const float*)pQ, sc_b1, (const int*)pRpP,
        (const int*)pAdjP, (__half*)pHh, n_stu);
    cudaStreamWaitEvent(0, eAY, 0);
    out_stu_h<<<gb_stu, 256, DYN_SMEM>>>((const __half*)pHh, (const __half*)pXWr,
                                         (const __half*)pMeanYh, (const int*)pDegP,
                                         sc_W2, sage_st_b, sc_b2,
                                         out_stu, stats, n_stu);
    bn_final_kernel<<<2048, 256>>>(out_stu, stats, 256, bn_stu_g, bn_stu_b, n_stu);

    // ---- join ----
    cudaStreamWaitEvent(0, eJoin, 0);
}